// round 6
// baseline (speedup 1.0000x reference)
#include <cuda_runtime.h>
#include <cuda_bf16.h>

#define BB 64
#define VV 64
#define TT 256
#define FF 64
#define NT  256
#define BPB 8     // batches per block
#define AP  68    // adj smem row pitch (floats): 272B, 16B-aligned, conflict-free LDS.128

// precomputed adj = sigmoid(A)*(1-I)+I   (4 MB scratch)
__device__ float g_adj[TT * VV * VV];

// ---------------------------------------------------------------------------
// k0: adj[t,v,w] = sigmoid(A[t,v,w]) off-diag, 1 on diag. 8 MB r/w, ~1.5 us.
// ---------------------------------------------------------------------------
__global__ __launch_bounds__(NT)
void k0_adj(const float* __restrict__ A, float* __restrict__ adjg)
{
    const int t   = blockIdx.x;
    const int tid = threadIdx.x;
    const float* At = A    + (size_t)t * VV * VV;
    float*       Ot = adjg + (size_t)t * VV * VV;
    #pragma unroll
    for (int k = 0; k < (VV * VV) / NT; ++k) {      // 16 iters, coalesced
        int i = tid + k * NT;
        int v = i >> 6, w = i & 63;
        float a = At[i];
        float s = 1.0f / (1.0f + __expf(-a));
        Ot[i] = (v == w) ? 1.0f : s;
    }
}

// ---------------------------------------------------------------------------
// fused: block = (t, bc). Load precomputed adj (float4, L2-hot), stage X slab,
// vectorized dot (LDS.128), then 8 x 16KB coalesced streaming stores.
// ---------------------------------------------------------------------------
__global__ __launch_bounds__(NT)
void gnn_fused(const float* __restrict__ X,
               const float* __restrict__ adjg,
               const float* __restrict__ W,
               float* __restrict__ out)
{
    __shared__ float adj[VV][AP];       // 17.4 KB
    __shared__ float xs[BPB][VV];       // 2 KB
    __shared__ float hs[BPB][VV];       // 2 KB

    const int t   = blockIdx.x;         // 0..255
    const int bc  = blockIdx.y;         // 0..7
    const int tid = threadIdx.x;
    const int b0  = bc * BPB;

    // ---- load adj tile: 1024 float4, 4 per thread (coalesced, L2-hot) ----
    const float4* Ag = reinterpret_cast<const float4*>(adjg + (size_t)t * VV * VV);
    #pragma unroll
    for (int k = 0; k < 4; ++k) {
        int i  = tid + k * NT;          // float4 index 0..1023
        int v  = i >> 4;
        int w4 = i & 15;
        float4 val = Ag[i];
        *reinterpret_cast<float4*>(&adj[v][w4 * 4]) = val;
    }

    // ---- stage xs[bl][w] = X[b0+bl, w, t] ----
    #pragma unroll
    for (int k = 0; k < (BPB * VV) / NT; ++k) {      // 2 iters
        int i  = tid + k * NT;
        int bl = i >> 6, w = i & 63;
        xs[bl][w] = X[((size_t)(b0 + bl) * VV + w) * TT + t];
    }
    __syncthreads();

    // ---- vectorized dot: thread owns (bl, v) and (bl, v+32) ----
    {
        const int bl = tid >> 5;        // 0..7 (fixed per warp)
        const int v  = tid & 31;        // 0..31
        float s0 = 0.0f, s1 = 0.0f;
        #pragma unroll
        for (int w4 = 0; w4 < 16; ++w4) {
            float4 x = *reinterpret_cast<const float4*>(&xs[bl][w4 * 4]);       // broadcast
            float4 p = *reinterpret_cast<const float4*>(&adj[v     ][w4 * 4]);  // conflict-free
            float4 q = *reinterpret_cast<const float4*>(&adj[v + 32][w4 * 4]);  // conflict-free
            s0 = fmaf(p.x, x.x, s0); s0 = fmaf(p.y, x.y, s0);
            s0 = fmaf(p.z, x.z, s0); s0 = fmaf(p.w, x.w, s0);
            s1 = fmaf(q.x, x.x, s1); s1 = fmaf(q.y, x.y, s1);
            s1 = fmaf(q.z, x.z, s1); s1 = fmaf(q.w, x.w, s1);
        }
        hs[bl][v]      = s0;
        hs[bl][v + 32] = s1;
    }

    // f index loop-invariant per thread -> hoist W vector
    const float4 wv = reinterpret_cast<const float4*>(W)[tid & 15];
    __syncthreads();

    // ---- expansion: 8 rows x 16 KB, float4 streaming stores ----
    #pragma unroll
    for (int bl = 0; bl < BPB; ++bl) {
        float4* o = reinterpret_cast<float4*>(
            out + ((size_t)(b0 + bl) * TT + t) * (VV * FF));
        #pragma unroll
        for (int j = 0; j < (VV * FF / 4) / NT; ++j) {   // 4 iters
            int p = j * NT + tid;                        // float4 idx, coalesced
            float h = hs[bl][p >> 4];
            float4 r;
            r.x = h * wv.x; r.y = h * wv.y; r.z = h * wv.z; r.w = h * wv.w;
            r.x = (r.x >= 0.0f) ? r.x : 0.01f * r.x;
            r.y = (r.y >= 0.0f) ? r.y : 0.01f * r.y;
            r.z = (r.z >= 0.0f) ? r.z : 0.01f * r.z;
            r.w = (r.w >= 0.0f) ? r.w : 0.01f * r.w;
            __stcs(&o[p], r);                            // evict-first stream
        }
    }
}

extern "C" void kernel_launch(void* const* d_in, const int* in_sizes, int n_in,
                              void* d_out, int out_size) {
    const float* X = (const float*)d_in[0];   // [64, 64, 256]
    const float* A = (const float*)d_in[1];   // [256, 64, 64]
    const float* W = (const float*)d_in[2];   // [64, 1]
    float* out = (float*)d_out;               // [64, 256, 4096]
    (void)in_sizes; (void)n_in; (void)out_size;

    float* adjg;
    cudaGetSymbolAddress((void**)&adjg, g_adj);

    k0_adj<<<TT, NT>>>(A, adjg);
    dim3 grid(TT, BB / BPB);                  // (256, 8)
    gnn_fused<<<grid, NT>>>(X, adjg, W, out);
}